// round 15
// baseline (speedup 1.0000x reference)
#include <cuda_runtime.h>
#include <cstdint>

#define F_FEAT 4096
#define HID    128
#define OUT3H  384      // 3*HID
#define IN_DIM 129      // HID + 1
#define BOUNDARY_V (-0.01f)
#define NTHREADS 384

// Cross-feature reduction scratch. Static zero-init; the epilogue block
// resets everything after consuming, so every graph replay starts identical.
__device__ float        g_C_acc[HID];
__device__ float        g_H_acc[HID];
__device__ unsigned int g_cnt_masked;
__device__ unsigned int g_done;

__device__ __forceinline__ float sigmoidf(float x) {
    return 1.0f / (1.0f + expf(-x));
}

__device__ __forceinline__ bool mask_at(const void* mptr, int f, int mode) {
    if (mode == 0)      return ((const unsigned char*)mptr)[f] != 0;
    else if (mode == 1) return ((const int*)mptr)[f] != 0;
    else                return ((const float*)mptr)[f] != 0.0f;
}

// ---------------------------------------------------------------------------
// Fused kernel (R14 design + streaming hints on ALL once-read streams):
// one feature per block, 384 threads = 12 warps.
//  - weight mat-vec, per-feature gate tensors, input staging: __ldcs
//  - H_curr output: __stcs
//  - minimal prologue; mask dtype detection overlaps the mat-vec
//  - bias added in the gate phase; last block runs MLP head epilogue
// ---------------------------------------------------------------------------
__global__ __launch_bounds__(NTHREADS, 4) void fused_kernel(
    const int*           __restrict__ tim,
    const float*         __restrict__ X,
    const void*          __restrict__ maskp,
    const float*         __restrict__ Ht,
    const int*           __restrict__ last_occured,
    const float*         __restrict__ c_t,
    const float*         __restrict__ Wl,    // (F, 384, 129)
    const float*         __restrict__ bl,    // (F, 384)
    const float*         __restrict__ xTw,   // (F, 256)
    const float*         __restrict__ xTb,   // (F, 256)
    const float*         __restrict__ dTw,   // (F, 384)
    const float*         __restrict__ ciw,   // (F, 128)
    const float*         __restrict__ cow,   // (F, 128)
    const float*         __restrict__ w1,    // (256, 256)
    const float*         __restrict__ b1,    // (256,)
    const float*         __restrict__ w2,    // (2, 256)
    const float*         __restrict__ b2,    // (2,)
    float*               __restrict__ out)   // full d_out
{
    const int f    = blockIdx.x;
    const int tid  = threadIdx.x;
    const int lane = tid & 31;
    const int warp = tid >> 5;

    __shared__ float s_inp[IN_DIM];
    __shared__ float s_out[OUT3H];
    __shared__ int   s_comb;
    __shared__ int   s_islast;
    __shared__ float s_feat[256];
    __shared__ float s_h1[256];

    float* __restrict__ outH = out + 2;           // (F, 128)

    // --- minimal prologue: stage input vector, init detection flag ---
    if (tid == 0) s_comb = 0;
    if (tid < IN_DIM)
        s_inp[tid] = (tid == 0) ? __ldcs(X + f)
                                : __ldcs(Ht + (size_t)f * HID + (tid - 1));
    __syncthreads();

    // Per-lane input registers (reused across all 32 rows this warp owns).
    const float in0 = s_inp[lane];
    const float in1 = s_inp[32 + lane];
    const float in2 = s_inp[64 + lane];
    const float in3 = s_inp[96 + lane];
    const float in4 = s_inp[128];

    const float* __restrict__ Wf = Wl + (size_t)f * OUT3H * IN_DIM;
    const int rbase = warp * 32;

    // --- mat-vec: warp-per-row lane-strided loads, streaming (evict-first) ---
    #pragma unroll 8
    for (int j = 0; j < 32; j++) {
        const int r = rbase + j;
        const float* __restrict__ wr = Wf + (size_t)r * IN_DIM;
        float acc = __ldcs(wr + lane)       * in0
                  + __ldcs(wr + 32 + lane)  * in1
                  + __ldcs(wr + 64 + lane)  * in2
                  + __ldcs(wr + 96 + lane)  * in3;
        if (lane == 0) acc += __ldcs(wr + 128) * in4;
        #pragma unroll
        for (int o = 16; o > 0; o >>= 1)
            acc += __shfl_xor_sync(0xffffffffu, acc, o);
        if (lane == 0) s_out[r] = acc;          // no bias preload: direct store
    }

    // --- mask dtype detection (overlaps mat-vec tail; result read after bar) ---
    {
        const uint32_t* mw = (const uint32_t*)maskp;
        int gt1 = 0, offnz = 0;
        #pragma unroll
        for (int i = tid; i < F_FEAT / 4; i += NTHREADS) {
            uint32_t w = mw[i];
            gt1   |= ((w & 0xFEFEFEFEu) != 0u) ? 1 : 0;   // any byte > 1
            offnz |= ((w & 0xFFFFFF00u) != 0u) ? 1 : 0;   // nonzero off-stride byte
        }
        int comb = (gt1 << 1) | offnz;
        #pragma unroll
        for (int o = 16; o > 0; o >>= 1)
            comb |= __shfl_xor_sync(0xffffffffu, comb, o);
        if (lane == 0 && comb) atomicOr(&s_comb, comb);
    }
    __syncthreads();

    // --- gate math on threads 0..127 ---
    if (tid < HID) {
        const int c = s_comb;
        const int mode = (c & 2) ? 2 : ((c & 1) ? 0 : 1);  // 2=f32, 0=u8, 1=i32
        const bool m = mask_at(maskp, f, mode);

        const int t = tid;
        const size_t f256 = (size_t)f * 256;
        const size_t f384 = (size_t)f * 384;
        const size_t f128 = (size_t)f * 128;

        const float gi_pre = s_out[t]           + __ldcs(bl + f384 + t);
        const float go_pre = s_out[HID + t]     + __ldcs(bl + f384 + HID + t);
        const float gc_pre = s_out[2 * HID + t] + __ldcs(bl + f384 + 2 * HID + t);

        const float x     = s_inp[0];
        const float delta = (float)(tim[0] - __ldcs(last_occured + f));

        const float xm1 = __ldcs(xTw + f256 + t)       * x + __ldcs(xTb + f256 + t);
        const float xm2 = __ldcs(xTw + f256 + HID + t) * x + __ldcs(xTb + f256 + HID + t);

        const float wd1 = __ldcs(dTw + f384 + t);
        float       wd2 = __ldcs(dTw + f384 + HID + t);
        if (t == 0) wd2 = fminf(wd2, BOUNDARY_V);   // clamp hits flat row H=128 only
        const float wdo = __ldcs(dTw + f384 + 2 * HID + t);

        const float T1 = sigmoidf(xm1 + sigmoidf(wd1 * delta));
        const float T2 = sigmoidf(xm2 + sigmoidf(wd2 * delta));

        const float ctv = c_t[t];
        const float gi  = sigmoidf(gi_pre + __ldcs(ciw + f128 + t) * ctv);
        const float gc  = tanhf(gc_pre);

        const float giT1    = gi * T1;
        const float c_tilde = (1.0f - giT1) * ctv + giT1 * gc;
        const float c_new   = (1.0f - gi)   * ctv + gi * T2 * gc;
        const float go      = sigmoidf(go_pre + __ldcs(cow + f128 + t) * c_tilde + wdo * delta);

        const float Hc = m ? (go * tanhf(c_tilde)) : 0.0f;

        __stcs(outH + f128 + t, Hc);   // any==0 fallback patched by epilogue

        if (m) {
            atomicAdd(&g_C_acc[t], c_new);
            atomicAdd(&g_H_acc[t], Hc);
            if (t == 0) atomicAdd(&g_cnt_masked, 1u);
        }
    }

    // --- last-block epilogue ---
    __threadfence();
    __syncthreads();
    if (tid == 0) {
        unsigned int old = atomicAdd(&g_done, 1u);
        s_islast = (old == (unsigned int)(F_FEAT - 1)) ? 1 : 0;
    }
    __syncthreads();
    if (!s_islast) return;

    __threadfence();   // acquire all other blocks' accumulator writes

    const unsigned int cnt = g_cnt_masked;
    const float cntf = fmaxf((float)cnt, 1.0f);

    if (cnt == 0) {
        // Degenerate mask.any()==0 case: H_curr = Ht. Rewrite output.
        for (int i = tid; i < F_FEAT * HID; i += NTHREADS)
            outH[i] = Ht[i];
    }

    if (tid < HID) {
        const float Cc = g_C_acc[tid] / cntf;
        s_feat[tid]       = Cc;
        s_feat[HID + tid] = g_H_acc[tid] / cntf;
        out[2 + (size_t)F_FEAT * HID + tid] = Cc;   // C_curr output
        // reset scratch for the next graph replay
        g_C_acc[tid] = 0.0f;
        g_H_acc[tid] = 0.0f;
    }
    if (tid == 0) { g_cnt_masked = 0u; g_done = 0u; }
    __syncthreads();

    if (tid < 256) {
        float acc = b1[tid];
        #pragma unroll 8
        for (int i = 0; i < 256; i++)
            acc += w1[tid * 256 + i] * s_feat[i];
        s_h1[tid] = fmaxf(acc, 0.0f);
    }
    __syncthreads();

    if (tid < 32) {
        float a0 = 0.0f, a1 = 0.0f;
        #pragma unroll
        for (int k = tid; k < 256; k += 32) {
            const float h = s_h1[k];
            a0 += w2[k]       * h;
            a1 += w2[256 + k] * h;
        }
        #pragma unroll
        for (int o = 16; o > 0; o >>= 1) {
            a0 += __shfl_xor_sync(0xffffffffu, a0, o);
            a1 += __shfl_xor_sync(0xffffffffu, a1, o);
        }
        if (tid == 0) {
            const float l0 = a0 + b2[0];
            const float l1 = a1 + b2[1];
            const float mx = fmaxf(l0, l1);
            const float e0 = expf(l0 - mx);
            const float e1 = expf(l1 - mx);
            const float s  = e0 + e1;
            out[0] = e0 / s;
            out[1] = e1 / s;
        }
    }
}

// ---------------------------------------------------------------------------
// Launch
// ---------------------------------------------------------------------------
extern "C" void kernel_launch(void* const* d_in, const int* in_sizes, int n_in,
                              void* d_out, int out_size) {
    const int*   tim   = (const int*)  d_in[0];
    const float* X     = (const float*)d_in[1];
    // d_in[2] = X_hap (unused by reference)
    const void*  maskp = (const void*) d_in[3];
    const float* Ht    = (const float*)d_in[4];
    // d_in[5] = Ct (unused by reference)
    const int*   lastoc= (const int*)  d_in[6];
    const float* c_t   = (const float*)d_in[7];
    const float* Wl    = (const float*)d_in[8];
    const float* bl    = (const float*)d_in[9];
    const float* xTw   = (const float*)d_in[10];
    const float* xTb   = (const float*)d_in[11];
    const float* dTw   = (const float*)d_in[12];
    const float* ciw   = (const float*)d_in[13];
    const float* cow   = (const float*)d_in[14];
    const float* w1    = (const float*)d_in[15];
    const float* b1    = (const float*)d_in[16];
    const float* w2    = (const float*)d_in[17];
    const float* b2    = (const float*)d_in[18];

    fused_kernel<<<F_FEAT, NTHREADS>>>(tim, X, maskp, Ht, lastoc, c_t,
                                       Wl, bl, xTw, xTb, dTw, ciw, cow,
                                       w1, b1, w2, b2, (float*)d_out);
}

// round 16
// speedup vs baseline: 1.0496x; 1.0496x over previous
#include <cuda_runtime.h>
#include <cstdint>

#define F_FEAT 4096
#define HID    128
#define OUT3H  384      // 3*HID
#define IN_DIM 129      // HID + 1
#define BOUNDARY_V (-0.01f)
#define NTHREADS 384

// Cross-feature reduction scratch. Static zero-init; the epilogue block
// resets everything after consuming, so every graph replay starts identical.
__device__ float        g_C_acc[HID];
__device__ float        g_H_acc[HID];
__device__ unsigned int g_cnt_masked;
__device__ unsigned int g_done;

__device__ __forceinline__ float sigmoidf(float x) {
    return 1.0f / (1.0f + expf(-x));
}

__device__ __forceinline__ bool mask_at(const void* mptr, int f, int mode) {
    if (mode == 0)      return ((const unsigned char*)mptr)[f] != 0;
    else if (mode == 1) return ((const int*)mptr)[f] != 0;
    else                return ((const float*)mptr)[f] != 0.0f;
}

// ---------------------------------------------------------------------------
// Fused kernel (R14 winner: weight-slab __ldcs only; + __stcs output stream):
// one feature per block, 384 threads = 12 warps.
//  - minimal prologue: stage s_inp (129 floats) + one barrier, then the
//    weight stream opens immediately (warp-per-row, lane-strided, __ldcs)
//  - all small gate-phase tensors at DEFAULT cache policy (best measured)
//  - H_curr output via __stcs (write-once stream, no L2 write-allocate)
//  - mask dtype detection overlaps the mat-vec (atomicOr, read after barrier)
//  - bias added in the gate phase instead of preloaded into s_out
//  - last block: finalize C_curr + MLP head + softmax, reset scratch
// ---------------------------------------------------------------------------
__global__ __launch_bounds__(NTHREADS, 4) void fused_kernel(
    const int*           __restrict__ tim,
    const float*         __restrict__ X,
    const void*          __restrict__ maskp,
    const float*         __restrict__ Ht,
    const int*           __restrict__ last_occured,
    const float*         __restrict__ c_t,
    const float*         __restrict__ Wl,    // (F, 384, 129)
    const float*         __restrict__ bl,    // (F, 384)
    const float*         __restrict__ xTw,   // (F, 256)
    const float*         __restrict__ xTb,   // (F, 256)
    const float*         __restrict__ dTw,   // (F, 384)
    const float*         __restrict__ ciw,   // (F, 128)
    const float*         __restrict__ cow,   // (F, 128)
    const float*         __restrict__ w1,    // (256, 256)
    const float*         __restrict__ b1,    // (256,)
    const float*         __restrict__ w2,    // (2, 256)
    const float*         __restrict__ b2,    // (2,)
    float*               __restrict__ out)   // full d_out
{
    const int f    = blockIdx.x;
    const int tid  = threadIdx.x;
    const int lane = tid & 31;
    const int warp = tid >> 5;

    __shared__ float s_inp[IN_DIM];
    __shared__ float s_out[OUT3H];
    __shared__ int   s_comb;
    __shared__ int   s_islast;
    __shared__ float s_feat[256];
    __shared__ float s_h1[256];

    float* __restrict__ outH = out + 2;           // (F, 128)

    // --- minimal prologue: stage input vector, init detection flag ---
    if (tid == 0) s_comb = 0;
    if (tid < IN_DIM)
        s_inp[tid] = (tid == 0) ? X[f] : Ht[(size_t)f * HID + (tid - 1)];
    __syncthreads();

    // Per-lane input registers (reused across all 32 rows this warp owns).
    const float in0 = s_inp[lane];
    const float in1 = s_inp[32 + lane];
    const float in2 = s_inp[64 + lane];
    const float in3 = s_inp[96 + lane];
    const float in4 = s_inp[128];

    const float* __restrict__ Wf = Wl + (size_t)f * OUT3H * IN_DIM;
    const int rbase = warp * 32;

    // --- mat-vec: warp-per-row lane-strided loads, streaming (evict-first) ---
    #pragma unroll 8
    for (int j = 0; j < 32; j++) {
        const int r = rbase + j;
        const float* __restrict__ wr = Wf + (size_t)r * IN_DIM;
        float acc = __ldcs(wr + lane)       * in0
                  + __ldcs(wr + 32 + lane)  * in1
                  + __ldcs(wr + 64 + lane)  * in2
                  + __ldcs(wr + 96 + lane)  * in3;
        if (lane == 0) acc += __ldcs(wr + 128) * in4;
        #pragma unroll
        for (int o = 16; o > 0; o >>= 1)
            acc += __shfl_xor_sync(0xffffffffu, acc, o);
        if (lane == 0) s_out[r] = acc;          // no bias preload: direct store
    }

    // --- mask dtype detection (overlaps mat-vec tail; result read after bar) ---
    {
        const uint32_t* mw = (const uint32_t*)maskp;
        int gt1 = 0, offnz = 0;
        #pragma unroll
        for (int i = tid; i < F_FEAT / 4; i += NTHREADS) {
            uint32_t w = mw[i];
            gt1   |= ((w & 0xFEFEFEFEu) != 0u) ? 1 : 0;   // any byte > 1
            offnz |= ((w & 0xFFFFFF00u) != 0u) ? 1 : 0;   // nonzero off-stride byte
        }
        int comb = (gt1 << 1) | offnz;
        #pragma unroll
        for (int o = 16; o > 0; o >>= 1)
            comb |= __shfl_xor_sync(0xffffffffu, comb, o);
        if (lane == 0 && comb) atomicOr(&s_comb, comb);
    }
    __syncthreads();

    // --- gate math on threads 0..127 ---
    if (tid < HID) {
        const int c = s_comb;
        const int mode = (c & 2) ? 2 : ((c & 1) ? 0 : 1);  // 2=f32, 0=u8, 1=i32
        const bool m = mask_at(maskp, f, mode);

        const int t = tid;
        const size_t f256 = (size_t)f * 256;
        const size_t f384 = (size_t)f * 384;
        const size_t f128 = (size_t)f * 128;

        const float gi_pre = s_out[t]           + bl[f384 + t];
        const float go_pre = s_out[HID + t]     + bl[f384 + HID + t];
        const float gc_pre = s_out[2 * HID + t] + bl[f384 + 2 * HID + t];

        const float x     = s_inp[0];
        const float delta = (float)(tim[0] - last_occured[f]);

        const float xm1 = xTw[f256 + t]       * x + xTb[f256 + t];
        const float xm2 = xTw[f256 + HID + t] * x + xTb[f256 + HID + t];

        const float wd1 = dTw[f384 + t];
        float       wd2 = dTw[f384 + HID + t];
        if (t == 0) wd2 = fminf(wd2, BOUNDARY_V);   // clamp hits flat row H=128 only
        const float wdo = dTw[f384 + 2 * HID + t];

        const float T1 = sigmoidf(xm1 + sigmoidf(wd1 * delta));
        const float T2 = sigmoidf(xm2 + sigmoidf(wd2 * delta));

        const float ctv = c_t[t];
        const float gi  = sigmoidf(gi_pre + ciw[f128 + t] * ctv);
        const float gc  = tanhf(gc_pre);

        const float giT1    = gi * T1;
        const float c_tilde = (1.0f - giT1) * ctv + giT1 * gc;
        const float c_new   = (1.0f - gi)   * ctv + gi * T2 * gc;
        const float go      = sigmoidf(go_pre + cow[f128 + t] * c_tilde + wdo * delta);

        const float Hc = m ? (go * tanhf(c_tilde)) : 0.0f;

        __stcs(outH + f128 + t, Hc);   // any==0 fallback patched by epilogue

        if (m) {
            atomicAdd(&g_C_acc[t], c_new);
            atomicAdd(&g_H_acc[t], Hc);
            if (t == 0) atomicAdd(&g_cnt_masked, 1u);
        }
    }

    // --- last-block epilogue ---
    __threadfence();
    __syncthreads();
    if (tid == 0) {
        unsigned int old = atomicAdd(&g_done, 1u);
        s_islast = (old == (unsigned int)(F_FEAT - 1)) ? 1 : 0;
    }
    __syncthreads();
    if (!s_islast) return;

    __threadfence();   // acquire all other blocks' accumulator writes

    const unsigned int cnt = g_cnt_masked;
    const float cntf = fmaxf((float)cnt, 1.0f);

    if (cnt == 0) {
        // Degenerate mask.any()==0 case: H_curr = Ht. Rewrite output.
        for (int i = tid; i < F_FEAT * HID; i += NTHREADS)
            outH[i] = Ht[i];
    }

    if (tid < HID) {
        const float Cc = g_C_acc[tid] / cntf;
        s_feat[tid]       = Cc;
        s_feat[HID + tid] = g_H_acc[tid] / cntf;
        out[2 + (size_t)F_FEAT * HID + tid] = Cc;   // C_curr output
        // reset scratch for the next graph replay
        g_C_acc[tid] = 0.0f;
        g_H_acc[tid] = 0.0f;
    }
    if (tid == 0) { g_cnt_masked = 0u; g_done = 0u; }
    __syncthreads();

    if (tid < 256) {
        float acc = b1[tid];
        #pragma unroll 8
        for (int i = 0; i < 256; i++)
            acc += w1[tid * 256 + i] * s_feat[i];
        s_h1[tid] = fmaxf(acc, 0.0f);
    }
    __syncthreads();

    if (tid < 32) {
        float a0 = 0.0f, a1 = 0.0f;
        #pragma unroll
        for (int k = tid; k < 256; k += 32) {
            const float h = s_h1[k];
            a0 += w2[k]       * h;
            a1 += w2[256 + k] * h;
        }
        #pragma unroll
        for (int o = 16; o > 0; o >>= 1) {
            a0 += __shfl_xor_sync(0xffffffffu, a0, o);
            a1 += __shfl_xor_sync(0xffffffffu, a1, o);
        }
        if (tid == 0) {
            const float l0 = a0 + b2[0];
            const float l1 = a1 + b2[1];
            const float mx = fmaxf(l0, l1);
            const float e0 = expf(l0 - mx);
            const float e1 = expf(l1 - mx);
            const float s  = e0 + e1;
            out[0] = e0 / s;
            out[1] = e1 / s;
        }
    }
}

// ---------------------------------------------------------------------------
// Launch
// ---------------------------------------------------------------------------
extern "C" void kernel_launch(void* const* d_in, const int* in_sizes, int n_in,
                              void* d_out, int out_size) {
    const int*   tim   = (const int*)  d_in[0];
    const float* X     = (const float*)d_in[1];
    // d_in[2] = X_hap (unused by reference)
    const void*  maskp = (const void*) d_in[3];
    const float* Ht    = (const float*)d_in[4];
    // d_in[5] = Ct (unused by reference)
    const int*   lastoc= (const int*)  d_in[6];
    const float* c_t   = (const float*)d_in[7];
    const float* Wl    = (const float*)d_in[8];
    const float* bl    = (const float*)d_in[9];
    const float* xTw   = (const float*)d_in[10];
    const float* xTb   = (const float*)d_in[11];
    const float* dTw   = (const float*)d_in[12];
    const float* ciw   = (const float*)d_in[13];
    const float* cow   = (const float*)d_in[14];
    const float* w1    = (const float*)d_in[15];
    const float* b1    = (const float*)d_in[16];
    const float* w2    = (const float*)d_in[17];
    const float* b2    = (const float*)d_in[18];

    fused_kernel<<<F_FEAT, NTHREADS>>>(tim, X, maskp, Ht, lastoc, c_t,
                                       Wl, bl, xTw, xTb, dTw, ciw, cow,
                                       w1, b1, w2, b2, (float*)d_out);
}